// round 5
// baseline (speedup 1.0000x reference)
#include <cuda_runtime.h>
#include <cuda_bf16.h>
#include <math.h>
#include <stdint.h>

// Problem constants
#define Vv 50257
#define Dd 384
#define Hh 6
#define HSs 64
#define Ll 6
#define Tt 256
#define Bb 8
#define BT (Bb*Tt)          // 2048 rows
#define QKVN (3*Hh*HSs)     // 1152
#define FF (4*Dd)           // 1536

// -------- device scratch (no allocation allowed) --------
__device__ float g_x   [BT*Dd];
__device__ float g_xn  [BT*Dd];
__device__ float g_qkv [BT*QKVN];
__device__ float g_att [BT*Dd];
__device__ float g_h1  [BT*FF];
__device__ float g_wpk [Ll*Dd*QKVN];

// ============================================================
// Embedding: x[b,t,:] = tok_emb[idx[b,t],:]
// ============================================================
__global__ void embed_kernel(const int* __restrict__ idx,
                             const float* __restrict__ tok,
                             float* __restrict__ x) {
    int gid = blockIdx.x * blockDim.x + threadIdx.x;
    if (gid >= BT * Dd) return;
    int row = gid / Dd;
    int d   = gid - row * Dd;
    x[gid] = tok[(size_t)idx[row] * Dd + d];
}

// ============================================================
// Pack Wq/Wk/Wv (L,H,D,HS) -> wpk[L][D][3*H*HS] row-major
// ============================================================
__global__ void pack_kernel(const float* __restrict__ Wq,
                            const float* __restrict__ Wk,
                            const float* __restrict__ Wv,
                            float* __restrict__ wp) {
    int gid = blockIdx.x * blockDim.x + threadIdx.x;
    const int total = Ll * Hh * Dd * HSs;
    if (gid >= total) return;
    int s = gid & (HSs - 1);
    int d = (gid >> 6) % Dd;
    int h = (gid / (HSs * Dd)) % Hh;
    int l = gid / (HSs * Dd * Hh);
    size_t src = (((size_t)(l * Hh + h) * Dd) + d) * HSs + s;
    size_t dstRow = (size_t)(l * Dd + d) * QKVN;
    int col = h * HSs + s;
    wp[dstRow + col]            = Wq[src];
    wp[dstRow + Dd + col]       = Wk[src];
    wp[dstRow + 2 * Dd + col]   = Wv[src];
}

// ============================================================
// LayerNorm: per-row (D=384), 128 threads/row, two-pass
// ============================================================
__global__ __launch_bounds__(128) void ln_kernel(const float* __restrict__ x,
                                                 const float* __restrict__ g,
                                                 const float* __restrict__ b,
                                                 float* __restrict__ y) {
    int row = blockIdx.x;
    const float* xr = x + (size_t)row * Dd;
    int tid = threadIdx.x;
    float v0 = xr[tid], v1 = xr[tid + 128], v2 = xr[tid + 256];
    float s = v0 + v1 + v2;
    __shared__ float red[4];
    #pragma unroll
    for (int o = 16; o; o >>= 1) s += __shfl_xor_sync(~0u, s, o);
    if ((tid & 31) == 0) red[tid >> 5] = s;
    __syncthreads();
    float mean = (red[0] + red[1] + red[2] + red[3]) * (1.0f / Dd);
    float d0 = v0 - mean, d1 = v1 - mean, d2 = v2 - mean;
    float q = d0 * d0 + d1 * d1 + d2 * d2;
    __syncthreads();
    #pragma unroll
    for (int o = 16; o; o >>= 1) q += __shfl_xor_sync(~0u, q, o);
    if ((tid & 31) == 0) red[tid >> 5] = q;
    __syncthreads();
    float var = (red[0] + red[1] + red[2] + red[3]) * (1.0f / Dd);
    float rstd = rsqrtf(var + 1e-5f);
    float* yr = y + (size_t)row * Dd;
    yr[tid]       = d0 * rstd * g[tid]       + b[tid];
    yr[tid + 128] = d1 * rstd * g[tid + 128] + b[tid + 128];
    yr[tid + 256] = d2 * rstd * g[tid + 256] + b[tid + 256];
}

// ============================================================
// RoPE (exact replica of reference semantics) on q and k in qkv buf
//   out[2i]   = -q[2i+1] * emb[t][32+i]
//   out[2i+1] =  q[2i]   * emb[t][i]
//   emb[t][m] = m even ? sin(t*exp(lg*m)) : cos(t*exp(lg*(m-1))),
//   lg = -ln(10000)/64
// ============================================================
__global__ void rope_kernel(float* __restrict__ qkv) {
    int gid = blockIdx.x * blockDim.x + threadIdx.x;
    const int total = Bb * Tt * Hh * 32;
    if (gid >= total) return;
    int i  = gid & 31;
    int h  = (gid >> 5) % Hh;
    int bt = gid / (32 * Hh);
    int t  = bt & (Tt - 1);
    const float lg = -9.210340371976184f / 64.0f;  // -ln(10000)/64
    float S, C;
    float tf = (float)t;
    if ((i & 1) == 0) {
        S = sinf(tf * expf(lg * (float)i));
        C = sinf(tf * expf(lg * (float)(32 + i)));
    } else {
        S = cosf(tf * expf(lg * (float)(i - 1)));
        C = cosf(tf * expf(lg * (float)(31 + i)));
    }
    size_t rowq = (size_t)bt * QKVN + h * HSs;
    float qe = qkv[rowq + 2 * i], qo = qkv[rowq + 2 * i + 1];
    qkv[rowq + 2 * i]     = -qo * C;
    qkv[rowq + 2 * i + 1] =  qe * S;
    float* kp = qkv + rowq + Dd;
    float ke = kp[2 * i], ko = kp[2 * i + 1];
    kp[2 * i]     = -ko * C;
    kp[2 * i + 1] =  ke * S;
}

// ============================================================
// Fused causal attention, flash-style online softmax in exp2 domain.
// grid = (B*H, 2 halves of 128 queries), block = 128 threads (1 query/thread)
// Key/Value tiles of 64 rows in static smem (32 KB).
// ============================================================
__global__ __launch_bounds__(128) void attn_kernel(const float* __restrict__ qkv,
                                                   float* __restrict__ att) {
    __shared__ __align__(16) float Ks[64 * 64];
    __shared__ __align__(16) float Vs[64 * 64];
    int b = blockIdx.x / Hh, h = blockIdx.x % Hh;
    int tid = threadIdx.x;
    int t = blockIdx.y * 128 + tid;
    size_t qrow = ((size_t)(b * Tt + t)) * QKVN + h * HSs;
    float qr[64];
    #pragma unroll
    for (int c = 0; c < 16; ++c) {
        float4 v = *(const float4*)(qkv + qrow + c * 4);
        qr[c*4+0] = v.x; qr[c*4+1] = v.y; qr[c*4+2] = v.z; qr[c*4+3] = v.w;
    }
    const float sc = 0.125f * 1.4426950408889634f;  // HS^-0.5 * log2(e)
    #pragma unroll
    for (int d = 0; d < 64; ++d) qr[d] *= sc;

    float mrun = -1e30f, ssum = 0.0f;
    float acc[64];
    #pragma unroll
    for (int d = 0; d < 64; ++d) acc[d] = 0.0f;

    int ntiles = blockIdx.y * 2 + 2;
    for (int tile = 0; tile < ntiles; ++tile) {
        #pragma unroll
        for (int u = 0; u < 8; ++u) {
            int e = tid + u * 128;           // float4 index 0..1023
            int j = e >> 4;
            int c = (e & 15) << 2;
            size_t src = ((size_t)(b * Tt + tile * 64 + j)) * QKVN + h * HSs + c;
            *(float4*)(Ks + j * 64 + c) = *(const float4*)(qkv + src + Dd);
            *(float4*)(Vs + j * 64 + c) = *(const float4*)(qkv + src + 2 * Dd);
        }
        __syncthreads();
        int jmax = t - tile * 64;            // inclusive
        if (jmax > 63) jmax = 63;
        for (int jj = 0; jj <= jmax; ++jj) {
            const float* kr = Ks + jj * 64;
            float s = 0.0f;
            #pragma unroll
            for (int d = 0; d < 64; ++d) s += qr[d] * kr[d];
            const float* vr = Vs + jj * 64;
            if (s <= mrun) {
                float p = exp2f(s - mrun);
                ssum += p;
                #pragma unroll
                for (int d = 0; d < 64; ++d) acc[d] += p * vr[d];
            } else {
                float corr = exp2f(mrun - s);
                ssum = ssum * corr + 1.0f;
                #pragma unroll
                for (int d = 0; d < 64; ++d) acc[d] = acc[d] * corr + vr[d];
                mrun = s;
            }
        }
        __syncthreads();
    }
    float inv = 1.0f / ssum;
    float* op = att + ((size_t)(b * Tt + t)) * Dd + h * HSs;
    #pragma unroll
    for (int c = 0; c < 16; ++c) {
        float4 v;
        v.x = acc[c*4] * inv; v.y = acc[c*4+1] * inv;
        v.z = acc[c*4+2] * inv; v.w = acc[c*4+3] * inv;
        *(float4*)(op + c * 4) = v;
    }
}

// ============================================================
// Tiled SGEMM: C(MxN) = A(MxK) @ B(KxN) [+bias][+res][relu]
// BM=128, BN=64, BK=16, 256 threads, 8x4 microtile.
// Requires: M % 128 == 0, K % 16 == 0. N arbitrary (bounds-checked).
// ============================================================
template<bool BIAS, bool RELU, bool RES>
__global__ __launch_bounds__(256) void sgemm_kernel(
    int M, int N, int K,
    const float* __restrict__ A,
    const float* __restrict__ B,
    const float* __restrict__ bias,
    const float* __restrict__ res,
    float* __restrict__ C) {
    constexpr int BM = 128, BN = 64, BK = 16, TM = 8, TN = 4;
    __shared__ __align__(16) float As[BK][BM];
    __shared__ __align__(16) float Bs[BK][BN];
    int tid = threadIdx.x;
    int m0 = blockIdx.y * BM;
    int n0 = blockIdx.x * BN;
    int tx = tid & 15;   // 0..15 col group
    int ty = tid >> 4;   // 0..15 row group
    float acc[TM][TN];
    #pragma unroll
    for (int i = 0; i < TM; ++i)
        #pragma unroll
        for (int j = 0; j < TN; ++j) acc[i][j] = 0.0f;

    int nk = K / BK;
    for (int kt = 0; kt < nk; ++kt) {
        int k0 = kt * BK;
        // A: 512 float4 per tile, 2 per thread, stored transposed
        #pragma unroll
        for (int u = 0; u < 2; ++u) {
            int qi = tid + u * 256;
            int r  = qi >> 2;
            int c4 = qi & 3;
            float4 av = *(const float4*)(A + (size_t)(m0 + r) * K + k0 + c4 * 4);
            As[c4*4+0][r] = av.x;
            As[c4*4+1][r] = av.y;
            As[c4*4+2][r] = av.z;
            As[c4*4+3][r] = av.w;
        }
        // B: 1024 floats, 4 consecutive per thread (scalar: N may be unaligned)
        {
            int e  = tid * 4;
            int kk = e >> 6;
            int cc = e & 63;
            const float* Brow = B + (size_t)(k0 + kk) * N + n0 + cc;
            #pragma unroll
            for (int j = 0; j < 4; ++j) {
                int n = n0 + cc + j;
                Bs[kk][cc + j] = (n < N) ? Brow[j] : 0.0f;
            }
        }
        __syncthreads();
        #pragma unroll
        for (int kk = 0; kk < BK; ++kk) {
            float4 a0 = *(const float4*)(&As[kk][ty * TM]);
            float4 a1 = *(const float4*)(&As[kk][ty * TM + 4]);
            float4 bb = *(const float4*)(&Bs[kk][tx * TN]);
            float a[TM] = {a0.x, a0.y, a0.z, a0.w, a1.x, a1.y, a1.z, a1.w};
            float bf[TN] = {bb.x, bb.y, bb.z, bb.w};
            #pragma unroll
            for (int i = 0; i < TM; ++i)
                #pragma unroll
                for (int j = 0; j < TN; ++j)
                    acc[i][j] += a[i] * bf[j];
        }
        __syncthreads();
    }
    #pragma unroll
    for (int i = 0; i < TM; ++i) {
        int m = m0 + ty * TM + i;
        #pragma unroll
        for (int j = 0; j < TN; ++j) {
            int n = n0 + tx * TN + j;
            if (n < N) {
                float v = acc[i][j];
                if (BIAS) v += bias[n];
                if (RES)  v += res[(size_t)m * N + n];
                if (RELU) v = fmaxf(v, 0.0f);
                C[(size_t)m * N + n] = v;
            }
        }
    }
}

// ============================================================
// Host orchestration (graph-capturable: kernel launches only)
// ============================================================
static inline dim3 gemm_grid(int M, int N) {
    return dim3((unsigned)((N + 63) / 64), (unsigned)(M / 128));
}

extern "C" void kernel_launch(void* const* d_in, const int* in_sizes, int n_in,
                              void* d_out, int out_size) {
    const int*   idx  = (const int*)  d_in[0];
    const float* tok  = (const float*)d_in[1];
    const float* Wq   = (const float*)d_in[2];
    const float* Wk   = (const float*)d_in[3];
    const float* Wv   = (const float*)d_in[4];
    const float* Wp   = (const float*)d_in[5];
    const float* bp   = (const float*)d_in[6];
    const float* W1   = (const float*)d_in[7];
    const float* b1   = (const float*)d_in[8];
    const float* W2   = (const float*)d_in[9];
    const float* b2   = (const float*)d_in[10];
    const float* ln1g = (const float*)d_in[11];
    const float* ln1b = (const float*)d_in[12];
    const float* ln2g = (const float*)d_in[13];
    const float* ln2b = (const float*)d_in[14];
    const float* lnfg = (const float*)d_in[15];
    const float* lnfb = (const float*)d_in[16];
    const float* lmW  = (const float*)d_in[17];
    const float* lmb  = (const float*)d_in[18];
    float* out = (float*)d_out;

    float *px, *pxn, *pqkv, *patt, *ph1, *pwp;
    cudaGetSymbolAddress((void**)&px,   g_x);
    cudaGetSymbolAddress((void**)&pxn,  g_xn);
    cudaGetSymbolAddress((void**)&pqkv, g_qkv);
    cudaGetSymbolAddress((void**)&patt, g_att);
    cudaGetSymbolAddress((void**)&ph1,  g_h1);
    cudaGetSymbolAddress((void**)&pwp,  g_wpk);

    // Pack qkv weights: L*H*D*HS = 884736 threads
    pack_kernel<<<(Ll*Hh*Dd*HSs + 255) / 256, 256>>>(Wq, Wk, Wv, pwp);
    // Embedding
    embed_kernel<<<(BT*Dd + 255) / 256, 256>>>(idx, tok, px);

    for (int l = 0; l < Ll; ++l) {
        // ln1
        ln_kernel<<<BT, 128>>>(px, ln1g + l * Dd, ln1b + l * Dd, pxn);
        // qkv = xn @ wpk[l]  (2048 x 1152)
        sgemm_kernel<false,false,false><<<gemm_grid(BT, QKVN), 256>>>(
            BT, QKVN, Dd, pxn, pwp + (size_t)l * Dd * QKVN, nullptr, nullptr, pqkv);
        // rope on q,k
        rope_kernel<<<(Bb*Tt*Hh*32 + 255) / 256, 256>>>(pqkv);
        // attention
        attn_kernel<<<dim3(Bb * Hh, 2), 128>>>(pqkv, patt);
        // x = x + att @ Wp[l] + bp[l]
        sgemm_kernel<true,false,true><<<gemm_grid(BT, Dd), 256>>>(
            BT, Dd, Dd, patt, Wp + (size_t)l * Dd * Dd, bp + l * Dd, px, px);
        // ln2
        ln_kernel<<<BT, 128>>>(px, ln2g + l * Dd, ln2b + l * Dd, pxn);
        // h1 = relu(xn @ W1[l] + b1[l])
        sgemm_kernel<true,true,false><<<gemm_grid(BT, FF), 256>>>(
            BT, FF, Dd, pxn, W1 + (size_t)l * Dd * FF, b1 + l * FF, nullptr, ph1);
        // x = x + h1 @ W2[l] + b2[l]
        sgemm_kernel<true,false,true><<<gemm_grid(BT, Dd), 256>>>(
            BT, Dd, FF, ph1, W2 + (size_t)l * FF * Dd, b2 + l * Dd, px, px);
    }
    // final LN
    ln_kernel<<<BT, 128>>>(px, lnfg, lnfb, pxn);
    // logits = xn @ lmW + lmb   (2048 x 50257)
    sgemm_kernel<true,false,false><<<gemm_grid(BT, Vv), 256>>>(
        BT, Vv, Dd, pxn, lmW, lmb, nullptr, out);
}

// round 6
// speedup vs baseline: 1.4313x; 1.4313x over previous
#include <cuda_runtime.h>
#include <cuda_bf16.h>
#include <math.h>
#include <stdint.h>

// Problem constants
#define Vv 50257
#define Dd 384
#define Hh 6
#define HSs 64
#define Ll 6
#define Tt 256
#define Bb 8
#define BT (Bb*Tt)          // 2048 rows
#define QKVN (3*Hh*HSs)     // 1152
#define FF (4*Dd)           // 1536

// -------- device scratch (no allocation allowed) --------
__device__ float g_x   [BT*Dd];
__device__ float g_xn  [BT*Dd];
__device__ float g_qkv [BT*QKVN];
__device__ float g_att [BT*Dd];
__device__ float g_h1  [BT*FF];
__device__ float g_wpk [Ll*Dd*QKVN];

// ============================================================
// Embedding: x[b,t,:] = tok_emb[idx[b,t],:]
// ============================================================
__global__ void embed_kernel(const int* __restrict__ idx,
                             const float* __restrict__ tok,
                             float* __restrict__ x) {
    int gid = blockIdx.x * blockDim.x + threadIdx.x;
    if (gid >= BT * Dd) return;
    int row = gid / Dd;
    int d   = gid - row * Dd;
    x[gid] = tok[(size_t)idx[row] * Dd + d];
}

// ============================================================
// Pack Wq/Wk/Wv (L,H,D,HS) -> wpk[L][D][3*H*HS] row-major
// ============================================================
__global__ void pack_kernel(const float* __restrict__ Wq,
                            const float* __restrict__ Wk,
                            const float* __restrict__ Wv,
                            float* __restrict__ wp) {
    int gid = blockIdx.x * blockDim.x + threadIdx.x;
    const int total = Ll * Hh * Dd * HSs;
    if (gid >= total) return;
    int s = gid & (HSs - 1);
    int d = (gid >> 6) % Dd;
    int h = (gid / (HSs * Dd)) % Hh;
    int l = gid / (HSs * Dd * Hh);
    size_t src = (((size_t)(l * Hh + h) * Dd) + d) * HSs + s;
    size_t dstRow = (size_t)(l * Dd + d) * QKVN;
    int col = h * HSs + s;
    wp[dstRow + col]            = Wq[src];
    wp[dstRow + Dd + col]       = Wk[src];
    wp[dstRow + 2 * Dd + col]   = Wv[src];
}

// ============================================================
// LayerNorm: per-row (D=384), 128 threads/row, two-pass
// ============================================================
__global__ __launch_bounds__(128) void ln_kernel(const float* __restrict__ x,
                                                 const float* __restrict__ g,
                                                 const float* __restrict__ b,
                                                 float* __restrict__ y) {
    int row = blockIdx.x;
    const float* xr = x + (size_t)row * Dd;
    int tid = threadIdx.x;
    float v0 = xr[tid], v1 = xr[tid + 128], v2 = xr[tid + 256];
    float s = v0 + v1 + v2;
    __shared__ float red[4];
    #pragma unroll
    for (int o = 16; o; o >>= 1) s += __shfl_xor_sync(~0u, s, o);
    if ((tid & 31) == 0) red[tid >> 5] = s;
    __syncthreads();
    float mean = (red[0] + red[1] + red[2] + red[3]) * (1.0f / Dd);
    float d0 = v0 - mean, d1 = v1 - mean, d2 = v2 - mean;
    float q = d0 * d0 + d1 * d1 + d2 * d2;
    __syncthreads();
    #pragma unroll
    for (int o = 16; o; o >>= 1) q += __shfl_xor_sync(~0u, q, o);
    if ((tid & 31) == 0) red[tid >> 5] = q;
    __syncthreads();
    float var = (red[0] + red[1] + red[2] + red[3]) * (1.0f / Dd);
    float rstd = rsqrtf(var + 1e-5f);
    float* yr = y + (size_t)row * Dd;
    yr[tid]       = d0 * rstd * g[tid]       + b[tid];
    yr[tid + 128] = d1 * rstd * g[tid + 128] + b[tid + 128];
    yr[tid + 256] = d2 * rstd * g[tid + 256] + b[tid + 256];
}

// ============================================================
// RoPE (exact replica of reference semantics) on q and k
// ============================================================
__global__ void rope_kernel(float* __restrict__ qkv) {
    int gid = blockIdx.x * blockDim.x + threadIdx.x;
    const int total = Bb * Tt * Hh * 32;
    if (gid >= total) return;
    int i  = gid & 31;
    int h  = (gid >> 5) % Hh;
    int bt = gid / (32 * Hh);
    int t  = bt & (Tt - 1);
    const float lg = -9.210340371976184f / 64.0f;  // -ln(10000)/64
    float S, C;
    float tf = (float)t;
    if ((i & 1) == 0) {
        S = sinf(tf * expf(lg * (float)i));
        C = sinf(tf * expf(lg * (float)(32 + i)));
    } else {
        S = cosf(tf * expf(lg * (float)(i - 1)));
        C = cosf(tf * expf(lg * (float)(31 + i)));
    }
    size_t rowq = (size_t)bt * QKVN + h * HSs;
    float qe = qkv[rowq + 2 * i], qo = qkv[rowq + 2 * i + 1];
    qkv[rowq + 2 * i]     = -qo * C;
    qkv[rowq + 2 * i + 1] =  qe * S;
    float* kp = qkv + rowq + Dd;
    float ke = kp[2 * i], ko = kp[2 * i + 1];
    kp[2 * i]     = -ko * C;
    kp[2 * i + 1] =  ke * S;
}

// ============================================================
// Fused causal attention, flash-style online softmax (exp2 domain)
// ============================================================
__global__ __launch_bounds__(128) void attn_kernel(const float* __restrict__ qkv,
                                                   float* __restrict__ att) {
    __shared__ __align__(16) float Ks[64 * 64];
    __shared__ __align__(16) float Vs[64 * 64];
    int b = blockIdx.x / Hh, h = blockIdx.x % Hh;
    int tid = threadIdx.x;
    int t = blockIdx.y * 128 + tid;
    size_t qrow = ((size_t)(b * Tt + t)) * QKVN + h * HSs;
    float qr[64];
    #pragma unroll
    for (int c = 0; c < 16; ++c) {
        float4 v = *(const float4*)(qkv + qrow + c * 4);
        qr[c*4+0] = v.x; qr[c*4+1] = v.y; qr[c*4+2] = v.z; qr[c*4+3] = v.w;
    }
    const float sc = 0.125f * 1.4426950408889634f;
    #pragma unroll
    for (int d = 0; d < 64; ++d) qr[d] *= sc;

    float mrun = -1e30f, ssum = 0.0f;
    float acc[64];
    #pragma unroll
    for (int d = 0; d < 64; ++d) acc[d] = 0.0f;

    int ntiles = blockIdx.y * 2 + 2;
    for (int tile = 0; tile < ntiles; ++tile) {
        #pragma unroll
        for (int u = 0; u < 8; ++u) {
            int e = tid + u * 128;
            int j = e >> 4;
            int c = (e & 15) << 2;
            size_t src = ((size_t)(b * Tt + tile * 64 + j)) * QKVN + h * HSs + c;
            *(float4*)(Ks + j * 64 + c) = *(const float4*)(qkv + src + Dd);
            *(float4*)(Vs + j * 64 + c) = *(const float4*)(qkv + src + 2 * Dd);
        }
        __syncthreads();
        int jmax = t - tile * 64;
        if (jmax > 63) jmax = 63;
        for (int jj = 0; jj <= jmax; ++jj) {
            const float* kr = Ks + jj * 64;
            float s = 0.0f;
            #pragma unroll
            for (int d = 0; d < 64; ++d) s += qr[d] * kr[d];
            const float* vr = Vs + jj * 64;
            if (s <= mrun) {
                float p = exp2f(s - mrun);
                ssum += p;
                #pragma unroll
                for (int d = 0; d < 64; ++d) acc[d] += p * vr[d];
            } else {
                float corr = exp2f(mrun - s);
                ssum = ssum * corr + 1.0f;
                #pragma unroll
                for (int d = 0; d < 64; ++d) acc[d] = acc[d] * corr + vr[d];
                mrun = s;
            }
        }
        __syncthreads();
    }
    float inv = 1.0f / ssum;
    float* op = att + ((size_t)(b * Tt + t)) * Dd + h * HSs;
    #pragma unroll
    for (int c = 0; c < 16; ++c) {
        float4 v;
        v.x = acc[c*4] * inv; v.y = acc[c*4+1] * inv;
        v.z = acc[c*4+2] * inv; v.w = acc[c*4+3] * inv;
        *(float4*)(op + c * 4) = v;
    }
}

// ============================================================
// Tensor-core tf32 GEMM: C = A(MxK) @ B(KxN) [+bias][+res][relu]
// mma.sync.m16n8k8.tf32, BM=128 BN=128 BK=16, 256 thr (8 warps 4x2),
// warptile 32x64. Requires M%128==0, K%16==0. N arbitrary.
// ============================================================
__device__ __forceinline__ float to_tf32(float x) {
    uint32_t u;
    asm("cvt.rna.tf32.f32 %0, %1;" : "=r"(u) : "f"(x));
    return __uint_as_float(u);
}

__device__ __forceinline__ void mma_tf32(float* c, const uint32_t* a,
                                         uint32_t b0, uint32_t b1) {
    asm volatile(
        "mma.sync.aligned.m16n8k8.row.col.f32.tf32.tf32.f32 "
        "{%0,%1,%2,%3}, {%4,%5,%6,%7}, {%8,%9}, {%0,%1,%2,%3};\n"
        : "+f"(c[0]), "+f"(c[1]), "+f"(c[2]), "+f"(c[3])
        : "r"(a[0]), "r"(a[1]), "r"(a[2]), "r"(a[3]), "r"(b0), "r"(b1));
}

template<bool BIAS, bool RELU, bool RES>
__global__ __launch_bounds__(256, 2) void tgemm_kernel(
    int M, int N, int K,
    const float* __restrict__ A,
    const float* __restrict__ B,
    const float* __restrict__ bias,
    const float* __restrict__ res,
    float* __restrict__ C) {
    constexpr int BM = 128, BN = 128, BK = 16;
    constexpr int AST = BM + 8;   // 136: conflict-free fragment LDS
    constexpr int BST = BN + 8;   // 136
    __shared__ float As[BK][AST]; // As[k][m] (transposed)
    __shared__ float Bs[BK][BST]; // Bs[k][n]

    int tid  = threadIdx.x;
    int warp = tid >> 5, lane = tid & 31;
    int gid  = lane >> 2, tig = lane & 3;
    int m0 = blockIdx.y * BM;
    int n0 = blockIdx.x * BN;
    int warpRow = (warp >> 1) * 32;
    int warpCol = (warp & 1) * 64;
    bool nAligned = ((N & 3) == 0);

    float c[2][8][4];
    #pragma unroll
    for (int im = 0; im < 2; ++im)
        #pragma unroll
        for (int in = 0; in < 8; ++in)
            #pragma unroll
            for (int r = 0; r < 4; ++r) c[im][in][r] = 0.0f;

    int nk = K / BK;
    for (int kt = 0; kt < nk; ++kt) {
        int k0 = kt * BK;
        // ---- load A tile: 128x16 floats, 2 float4 per thread, store transposed
        #pragma unroll
        for (int u = 0; u < 2; ++u) {
            int q  = tid + u * 256;
            int r  = q >> 2;           // 0..127
            int c4 = (q & 3) * 4;      // 0,4,8,12
            float4 v = *(const float4*)(A + (size_t)(m0 + r) * K + k0 + c4);
            As[c4 + 0][r] = to_tf32(v.x);
            As[c4 + 1][r] = to_tf32(v.y);
            As[c4 + 2][r] = to_tf32(v.z);
            As[c4 + 3][r] = to_tf32(v.w);
        }
        // ---- load B tile: 16x128 floats
        if (nAligned) {
            #pragma unroll
            for (int u = 0; u < 2; ++u) {
                int q  = tid + u * 256;
                int kk = q >> 5;
                int cc = (q & 31) * 4;
                float4 v = *(const float4*)(B + (size_t)(k0 + kk) * N + n0 + cc);
                float4 w;
                w.x = to_tf32(v.x); w.y = to_tf32(v.y);
                w.z = to_tf32(v.z); w.w = to_tf32(v.w);
                *(float4*)(&Bs[kk][cc]) = w;
            }
        } else {
            #pragma unroll
            for (int u = 0; u < 8; ++u) {
                int e  = tid + u * 256;
                int kk = e >> 7;
                int cc = e & 127;
                int n  = n0 + cc;
                float v = (n < N) ? B[(size_t)(k0 + kk) * N + n] : 0.0f;
                Bs[kk][cc] = to_tf32(v);
            }
        }
        __syncthreads();
        // ---- compute: 2 k-steps of 8
        #pragma unroll
        for (int ks = 0; ks < 2; ++ks) {
            int kb = ks * 8;
            uint32_t a[2][4];
            #pragma unroll
            for (int im = 0; im < 2; ++im) {
                int mb = warpRow + im * 16;
                a[im][0] = __float_as_uint(As[kb + tig    ][mb + gid    ]);
                a[im][1] = __float_as_uint(As[kb + tig    ][mb + gid + 8]);
                a[im][2] = __float_as_uint(As[kb + tig + 4][mb + gid    ]);
                a[im][3] = __float_as_uint(As[kb + tig + 4][mb + gid + 8]);
            }
            #pragma unroll
            for (int in = 0; in < 8; ++in) {
                int nb = warpCol + in * 8 + gid;
                uint32_t b0 = __float_as_uint(Bs[kb + tig    ][nb]);
                uint32_t b1 = __float_as_uint(Bs[kb + tig + 4][nb]);
                mma_tf32(c[0][in], a[0], b0, b1);
                mma_tf32(c[1][in], a[1], b0, b1);
            }
        }
        __syncthreads();
    }
    // ---- epilogue
    #pragma unroll
    for (int im = 0; im < 2; ++im) {
        int mb = m0 + warpRow + im * 16 + gid;
        #pragma unroll
        for (int in = 0; in < 8; ++in) {
            int n = n0 + warpCol + in * 8 + tig * 2;
            #pragma unroll
            for (int j = 0; j < 2; ++j) {
                int nn = n + j;
                if (nn < N) {
                    float bv = BIAS ? bias[nn] : 0.0f;
                    float v0 = c[im][in][j]     + bv;
                    float v1 = c[im][in][j + 2] + bv;
                    int m1 = mb, m2 = mb + 8;
                    if (RES) {
                        v0 += res[(size_t)m1 * N + nn];
                        v1 += res[(size_t)m2 * N + nn];
                    }
                    if (RELU) { v0 = fmaxf(v0, 0.0f); v1 = fmaxf(v1, 0.0f); }
                    C[(size_t)m1 * N + nn] = v0;
                    C[(size_t)m2 * N + nn] = v1;
                }
            }
        }
    }
}

// ============================================================
// Host orchestration (graph-capturable: kernel launches only)
// ============================================================
static inline dim3 tgrid(int M, int N) {
    return dim3((unsigned)((N + 127) / 128), (unsigned)(M / 128));
}

extern "C" void kernel_launch(void* const* d_in, const int* in_sizes, int n_in,
                              void* d_out, int out_size) {
    const int*   idx  = (const int*)  d_in[0];
    const float* tok  = (const float*)d_in[1];
    const float* Wq   = (const float*)d_in[2];
    const float* Wk   = (const float*)d_in[3];
    const float* Wv   = (const float*)d_in[4];
    const float* Wp   = (const float*)d_in[5];
    const float* bp   = (const float*)d_in[6];
    const float* W1   = (const float*)d_in[7];
    const float* b1   = (const float*)d_in[8];
    const float* W2   = (const float*)d_in[9];
    const float* b2   = (const float*)d_in[10];
    const float* ln1g = (const float*)d_in[11];
    const float* ln1b = (const float*)d_in[12];
    const float* ln2g = (const float*)d_in[13];
    const float* ln2b = (const float*)d_in[14];
    const float* lnfg = (const float*)d_in[15];
    const float* lnfb = (const float*)d_in[16];
    const float* lmW  = (const float*)d_in[17];
    const float* lmb  = (const float*)d_in[18];
    float* out = (float*)d_out;

    float *px, *pxn, *pqkv, *patt, *ph1, *pwp;
    cudaGetSymbolAddress((void**)&px,   g_x);
    cudaGetSymbolAddress((void**)&pxn,  g_xn);
    cudaGetSymbolAddress((void**)&pqkv, g_qkv);
    cudaGetSymbolAddress((void**)&patt, g_att);
    cudaGetSymbolAddress((void**)&ph1,  g_h1);
    cudaGetSymbolAddress((void**)&pwp,  g_wpk);

    pack_kernel<<<(Ll*Hh*Dd*HSs + 255) / 256, 256>>>(Wq, Wk, Wv, pwp);
    embed_kernel<<<(BT*Dd + 255) / 256, 256>>>(idx, tok, px);

    for (int l = 0; l < Ll; ++l) {
        ln_kernel<<<BT, 128>>>(px, ln1g + l * Dd, ln1b + l * Dd, pxn);
        tgemm_kernel<false,false,false><<<tgrid(BT, QKVN), 256>>>(
            BT, QKVN, Dd, pxn, pwp + (size_t)l * Dd * QKVN, nullptr, nullptr, pqkv);
        rope_kernel<<<(Bb*Tt*Hh*32 + 255) / 256, 256>>>(pqkv);
        attn_kernel<<<dim3(Bb * Hh, 2), 128>>>(pqkv, patt);
        tgemm_kernel<true,false,true><<<tgrid(BT, Dd), 256>>>(
            BT, Dd, Dd, patt, Wp + (size_t)l * Dd * Dd, bp + l * Dd, px, px);
        ln_kernel<<<BT, 128>>>(px, ln2g + l * Dd, ln2b + l * Dd, pxn);
        tgemm_kernel<true,true,false><<<tgrid(BT, FF), 256>>>(
            BT, FF, Dd, pxn, W1 + (size_t)l * Dd * FF, b1 + l * FF, nullptr, ph1);
        tgemm_kernel<true,false,true><<<tgrid(BT, Dd), 256>>>(
            BT, Dd, FF, ph1, W2 + (size_t)l * FF * Dd, b2 + l * Dd, px, px);
    }
    ln_kernel<<<BT, 128>>>(px, lnfg, lnfb, pxn);
    tgemm_kernel<true,false,false><<<tgrid(BT, Vv), 256>>>(
        BT, Vv, Dd, pxn, lmW, lmb, nullptr, out);
}

// round 7
// speedup vs baseline: 1.7925x; 1.2524x over previous
#include <cuda_runtime.h>
#include <cuda_bf16.h>
#include <math.h>
#include <stdint.h>

// Problem constants
#define Vv 50257
#define Dd 384
#define Hh 6
#define HSs 64
#define Ll 6
#define Tt 256
#define Bb 8
#define BT (Bb*Tt)          // 2048 rows
#define QKVN (3*Hh*HSs)     // 1152
#define FF (4*Dd)           // 1536

// -------- device scratch (no allocation allowed) --------
__device__ float g_x   [BT*Dd];
__device__ float g_xn  [BT*Dd];
__device__ float g_qkv [BT*QKVN];
__device__ float g_att [BT*Dd];
__device__ float g_h1  [BT*FF];
__device__ float g_wpk [Ll*Dd*QKVN];

// ============================================================
// cp.async helpers
// ============================================================
__device__ __forceinline__ void cp_async16(void* dst, const void* src) {
    uint32_t s = (uint32_t)__cvta_generic_to_shared(dst);
    asm volatile("cp.async.cg.shared.global [%0], [%1], 16;\n" :: "r"(s), "l"(src));
}
__device__ __forceinline__ void cp_async4(void* dst, const void* src, int pred) {
    uint32_t s = (uint32_t)__cvta_generic_to_shared(dst);
    int sz = pred ? 4 : 0;   // src-size 0 => zero-fill, no gmem read
    asm volatile("cp.async.ca.shared.global [%0], [%1], 4, %2;\n" :: "r"(s), "l"(src), "r"(sz));
}
#define CP_COMMIT() asm volatile("cp.async.commit_group;\n" ::: "memory")
#define CP_WAIT0()  asm volatile("cp.async.wait_group 0;\n" ::: "memory")

__device__ __forceinline__ uint32_t ld_tf32(float x) {
    uint32_t u;
    asm("cvt.rna.tf32.f32 %0, %1;" : "=r"(u) : "f"(x));
    return u;
}

__device__ __forceinline__ void mma_tf32(float* c, const uint32_t* a,
                                         uint32_t b0, uint32_t b1) {
    asm volatile(
        "mma.sync.aligned.m16n8k8.row.col.f32.tf32.tf32.f32 "
        "{%0,%1,%2,%3}, {%4,%5,%6,%7}, {%8,%9}, {%0,%1,%2,%3};\n"
        : "+f"(c[0]), "+f"(c[1]), "+f"(c[2]), "+f"(c[3])
        : "r"(a[0]), "r"(a[1]), "r"(a[2]), "r"(a[3]), "r"(b0), "r"(b1));
}

// ============================================================
// Embedding
// ============================================================
__global__ void embed_kernel(const int* __restrict__ idx,
                             const float* __restrict__ tok,
                             float* __restrict__ x) {
    int gid = blockIdx.x * blockDim.x + threadIdx.x;
    if (gid >= BT * Dd) return;
    int row = gid / Dd;
    int d   = gid - row * Dd;
    x[gid] = tok[(size_t)idx[row] * Dd + d];
}

// ============================================================
// Pack Wq/Wk/Wv (L,H,D,HS) -> wpk[L][D][3*H*HS]
// ============================================================
__global__ void pack_kernel(const float* __restrict__ Wq,
                            const float* __restrict__ Wk,
                            const float* __restrict__ Wv,
                            float* __restrict__ wp) {
    int gid = blockIdx.x * blockDim.x + threadIdx.x;
    const int total = Ll * Hh * Dd * HSs;
    if (gid >= total) return;
    int s = gid & (HSs - 1);
    int d = (gid >> 6) % Dd;
    int h = (gid / (HSs * Dd)) % Hh;
    int l = gid / (HSs * Dd * Hh);
    size_t src = (((size_t)(l * Hh + h) * Dd) + d) * HSs + s;
    size_t dstRow = (size_t)(l * Dd + d) * QKVN;
    int col = h * HSs + s;
    wp[dstRow + col]            = Wq[src];
    wp[dstRow + Dd + col]       = Wk[src];
    wp[dstRow + 2 * Dd + col]   = Wv[src];
}

// ============================================================
// LayerNorm (D=384), 128 threads/row
// ============================================================
__global__ __launch_bounds__(128) void ln_kernel(const float* __restrict__ x,
                                                 const float* __restrict__ g,
                                                 const float* __restrict__ b,
                                                 float* __restrict__ y) {
    int row = blockIdx.x;
    const float* xr = x + (size_t)row * Dd;
    int tid = threadIdx.x;
    float v0 = xr[tid], v1 = xr[tid + 128], v2 = xr[tid + 256];
    float s = v0 + v1 + v2;
    __shared__ float red[4];
    #pragma unroll
    for (int o = 16; o; o >>= 1) s += __shfl_xor_sync(~0u, s, o);
    if ((tid & 31) == 0) red[tid >> 5] = s;
    __syncthreads();
    float mean = (red[0] + red[1] + red[2] + red[3]) * (1.0f / Dd);
    float d0 = v0 - mean, d1 = v1 - mean, d2 = v2 - mean;
    float q = d0 * d0 + d1 * d1 + d2 * d2;
    __syncthreads();
    #pragma unroll
    for (int o = 16; o; o >>= 1) q += __shfl_xor_sync(~0u, q, o);
    if ((tid & 31) == 0) red[tid >> 5] = q;
    __syncthreads();
    float var = (red[0] + red[1] + red[2] + red[3]) * (1.0f / Dd);
    float rstd = rsqrtf(var + 1e-5f);
    float* yr = y + (size_t)row * Dd;
    yr[tid]       = d0 * rstd * g[tid]       + b[tid];
    yr[tid + 128] = d1 * rstd * g[tid + 128] + b[tid + 128];
    yr[tid + 256] = d2 * rstd * g[tid + 256] + b[tid + 256];
}

// ============================================================
// RoPE (exact replica of reference semantics)
// ============================================================
__global__ void rope_kernel(float* __restrict__ qkv) {
    int gid = blockIdx.x * blockDim.x + threadIdx.x;
    const int total = Bb * Tt * Hh * 32;
    if (gid >= total) return;
    int i  = gid & 31;
    int h  = (gid >> 5) % Hh;
    int bt = gid / (32 * Hh);
    int t  = bt & (Tt - 1);
    const float lg = -9.210340371976184f / 64.0f;
    float S, C;
    float tf = (float)t;
    if ((i & 1) == 0) {
        S = sinf(tf * expf(lg * (float)i));
        C = sinf(tf * expf(lg * (float)(32 + i)));
    } else {
        S = cosf(tf * expf(lg * (float)(i - 1)));
        C = cosf(tf * expf(lg * (float)(31 + i)));
    }
    size_t rowq = (size_t)bt * QKVN + h * HSs;
    float qe = qkv[rowq + 2 * i], qo = qkv[rowq + 2 * i + 1];
    qkv[rowq + 2 * i]     = -qo * C;
    qkv[rowq + 2 * i + 1] =  qe * S;
    float* kp = qkv + rowq + Dd;
    float ke = kp[2 * i], ko = kp[2 * i + 1];
    kp[2 * i]     = -ko * C;
    kp[2 * i + 1] =  ke * S;
}

// ============================================================
// Fused causal attention (flash-style, exp2 domain)
// ============================================================
__global__ __launch_bounds__(128) void attn_kernel(const float* __restrict__ qkv,
                                                   float* __restrict__ att) {
    __shared__ __align__(16) float Ks[64 * 64];
    __shared__ __align__(16) float Vs[64 * 64];
    int b = blockIdx.x / Hh, h = blockIdx.x % Hh;
    int tid = threadIdx.x;
    int t = blockIdx.y * 128 + tid;
    size_t qrow = ((size_t)(b * Tt + t)) * QKVN + h * HSs;
    float qr[64];
    #pragma unroll
    for (int c = 0; c < 16; ++c) {
        float4 v = *(const float4*)(qkv + qrow + c * 4);
        qr[c*4+0] = v.x; qr[c*4+1] = v.y; qr[c*4+2] = v.z; qr[c*4+3] = v.w;
    }
    const float sc = 0.125f * 1.4426950408889634f;
    #pragma unroll
    for (int d = 0; d < 64; ++d) qr[d] *= sc;

    float mrun = -1e30f, ssum = 0.0f;
    float acc[64];
    #pragma unroll
    for (int d = 0; d < 64; ++d) acc[d] = 0.0f;

    int ntiles = blockIdx.y * 2 + 2;
    for (int tile = 0; tile < ntiles; ++tile) {
        #pragma unroll
        for (int u = 0; u < 8; ++u) {
            int e = tid + u * 128;
            int j = e >> 4;
            int c = (e & 15) << 2;
            size_t src = ((size_t)(b * Tt + tile * 64 + j)) * QKVN + h * HSs + c;
            *(float4*)(Ks + j * 64 + c) = *(const float4*)(qkv + src + Dd);
            *(float4*)(Vs + j * 64 + c) = *(const float4*)(qkv + src + 2 * Dd);
        }
        __syncthreads();
        int jmax = t - tile * 64;
        if (jmax > 63) jmax = 63;
        for (int jj = 0; jj <= jmax; ++jj) {
            const float* kr = Ks + jj * 64;
            float s = 0.0f;
            #pragma unroll
            for (int d = 0; d < 64; ++d) s += qr[d] * kr[d];
            const float* vr = Vs + jj * 64;
            if (s <= mrun) {
                float p = exp2f(s - mrun);
                ssum += p;
                #pragma unroll
                for (int d = 0; d < 64; ++d) acc[d] += p * vr[d];
            } else {
                float corr = exp2f(mrun - s);
                ssum = ssum * corr + 1.0f;
                #pragma unroll
                for (int d = 0; d < 64; ++d) acc[d] = acc[d] * corr + vr[d];
                mrun = s;
            }
        }
        __syncthreads();
    }
    float inv = 1.0f / ssum;
    float* op = att + ((size_t)(b * Tt + t)) * Dd + h * HSs;
    #pragma unroll
    for (int c = 0; c < 16; ++c) {
        float4 v;
        v.x = acc[c*4] * inv; v.y = acc[c*4+1] * inv;
        v.z = acc[c*4+2] * inv; v.w = acc[c*4+3] * inv;
        *(float4*)(op + c * 4) = v;
    }
}

// ============================================================
// Pipelined tf32 tensor-core GEMM (cp.async, double-buffered)
// C = A(MxK) @ B(KxN) [+bias][+res][relu]
// BN=128, BK=16. BM=128 (256 thr, 8 warps 4x2) or BM=64 (128 thr, 4 warps 2x2).
// Warptile 32x64. M%BM==0, K%16==0.
// ALIGNED: N%128==0 (16B cp.async). else: 4B cp.async, bounds-guarded.
// ============================================================
template<int BM, bool ALIGNED, bool BIAS, bool RELU, bool RES>
__global__ __launch_bounds__(BM == 128 ? 256 : 128, BM == 128 ? 2 : 4)
void tgemm_kernel(
    int M, int N, int K,
    const float* __restrict__ A,
    const float* __restrict__ B,
    const float* __restrict__ bias,
    const float* __restrict__ res,
    float* __restrict__ C) {
    constexpr int BN = 128, BK = 16;
    constexpr int THREADS = (BM == 128) ? 256 : 128;
    constexpr int SA = BK + 4;    // 20: fragment LDS conflict-free
    constexpr int SB = BN + 8;    // 136
    __shared__ float As[2][BM][SA];
    __shared__ float Bs[2][BK][SB];

    int tid  = threadIdx.x;
    int warp = tid >> 5, lane = tid & 31;
    int gid  = lane >> 2, tig = lane & 3;
    int m0 = blockIdx.y * BM;
    int n0 = blockIdx.x * BN;
    int warpRow = (warp >> 1) * 32;
    int warpCol = (warp & 1) * 64;

    float c[2][8][4];
    #pragma unroll
    for (int im = 0; im < 2; ++im)
        #pragma unroll
        for (int in = 0; in < 8; ++in)
            #pragma unroll
            for (int r = 0; r < 4; ++r) c[im][in][r] = 0.0f;

    int nk = K / BK;

    auto load_tiles = [&](int kt, int buf) {
        int k0 = kt * BK;
        // A tile: BM x 16 floats = BM*4 16B-chunks
        #pragma unroll
        for (int u = 0; u < (BM * 4) / THREADS; ++u) {
            int q  = tid + u * THREADS;
            int r  = q >> 2;
            int c4 = (q & 3) * 4;
            cp_async16(&As[buf][r][c4], A + (size_t)(m0 + r) * K + k0 + c4);
        }
        // B tile: 16 x 128 floats
        if (ALIGNED) {
            #pragma unroll
            for (int u = 0; u < 512 / THREADS; ++u) {
                int q  = tid + u * THREADS;
                int kk = q >> 5;
                int cc = (q & 31) * 4;
                cp_async16(&Bs[buf][kk][cc], B + (size_t)(k0 + kk) * N + n0 + cc);
            }
        } else {
            #pragma unroll
            for (int u = 0; u < 2048 / THREADS; ++u) {
                int e  = tid + u * THREADS;
                int kk = e >> 7;
                int cc = e & 127;
                int n  = n0 + cc;
                int ok = (n < N);
                const float* src = B + (size_t)(k0 + kk) * N + (ok ? n : 0);
                cp_async4(&Bs[buf][kk][cc], src, ok);
            }
        }
    };

    load_tiles(0, 0);
    CP_COMMIT();

    for (int kt = 0; kt < nk; ++kt) {
        int cur = kt & 1;
        CP_WAIT0();
        __syncthreads();
        if (kt + 1 < nk) {
            load_tiles(kt + 1, 1 - cur);
            CP_COMMIT();
        }
        #pragma unroll
        for (int ks = 0; ks < 2; ++ks) {
            int kb = ks * 8;
            uint32_t a[2][4];
            #pragma unroll
            for (int im = 0; im < 2; ++im) {
                int mb = warpRow + im * 16;
                a[im][0] = ld_tf32(As[cur][mb + gid    ][kb + tig    ]);
                a[im][1] = ld_tf32(As[cur][mb + gid + 8][kb + tig    ]);
                a[im][2] = ld_tf32(As[cur][mb + gid    ][kb + tig + 4]);
                a[im][3] = ld_tf32(As[cur][mb + gid + 8][kb + tig + 4]);
            }
            #pragma unroll
            for (int in = 0; in < 8; ++in) {
                int nb = warpCol + in * 8 + gid;
                uint32_t b0 = ld_tf32(Bs[cur][kb + tig    ][nb]);
                uint32_t b1 = ld_tf32(Bs[cur][kb + tig + 4][nb]);
                mma_tf32(c[0][in], a[0], b0, b1);
                mma_tf32(c[1][in], a[1], b0, b1);
            }
        }
        __syncthreads();
    }
    // epilogue
    #pragma unroll
    for (int im = 0; im < 2; ++im) {
        int mb = m0 + warpRow + im * 16 + gid;
        #pragma unroll
        for (int in = 0; in < 8; ++in) {
            int n = n0 + warpCol + in * 8 + tig * 2;
            #pragma unroll
            for (int j = 0; j < 2; ++j) {
                int nn = n + j;
                if (nn < N) {
                    float bv = BIAS ? bias[nn] : 0.0f;
                    float v0 = c[im][in][j]     + bv;
                    float v1 = c[im][in][j + 2] + bv;
                    int m1 = mb, m2 = mb + 8;
                    if (RES) {
                        v0 += res[(size_t)m1 * N + nn];
                        v1 += res[(size_t)m2 * N + nn];
                    }
                    if (RELU) { v0 = fmaxf(v0, 0.0f); v1 = fmaxf(v1, 0.0f); }
                    C[(size_t)m1 * N + nn] = v0;
                    C[(size_t)m2 * N + nn] = v1;
                }
            }
        }
    }
}

// ============================================================
// Host orchestration
// ============================================================
extern "C" void kernel_launch(void* const* d_in, const int* in_sizes, int n_in,
                              void* d_out, int out_size) {
    const int*   idx  = (const int*)  d_in[0];
    const float* tok  = (const float*)d_in[1];
    const float* Wq   = (const float*)d_in[2];
    const float* Wk   = (const float*)d_in[3];
    const float* Wv   = (const float*)d_in[4];
    const float* Wp   = (const float*)d_in[5];
    const float* bp   = (const float*)d_in[6];
    const float* W1   = (const float*)d_in[7];
    const float* b1   = (const float*)d_in[8];
    const float* W2   = (const float*)d_in[9];
    const float* b2   = (const float*)d_in[10];
    const float* ln1g = (const float*)d_in[11];
    const float* ln1b = (const float*)d_in[12];
    const float* ln2g = (const float*)d_in[13];
    const float* ln2b = (const float*)d_in[14];
    const float* lnfg = (const float*)d_in[15];
    const float* lnfb = (const float*)d_in[16];
    const float* lmW  = (const float*)d_in[17];
    const float* lmb  = (const float*)d_in[18];
    float* out = (float*)d_out;

    float *px, *pxn, *pqkv, *patt, *ph1, *pwp;
    cudaGetSymbolAddress((void**)&px,   g_x);
    cudaGetSymbolAddress((void**)&pxn,  g_xn);
    cudaGetSymbolAddress((void**)&pqkv, g_qkv);
    cudaGetSymbolAddress((void**)&patt, g_att);
    cudaGetSymbolAddress((void**)&ph1,  g_h1);
    cudaGetSymbolAddress((void**)&pwp,  g_wpk);

    pack_kernel<<<(Ll*Hh*Dd*HSs + 255) / 256, 256>>>(Wq, Wk, Wv, pwp);
    embed_kernel<<<(BT*Dd + 255) / 256, 256>>>(idx, tok, px);

    for (int l = 0; l < Ll; ++l) {
        ln_kernel<<<BT, 128>>>(px, ln1g + l * Dd, ln1b + l * Dd, pxn);
        // qkv = xn @ wpk[l]  (2048 x 1152 x 384)
        tgemm_kernel<128, true, false,false,false>
            <<<dim3(QKVN/128, BT/128), 256>>>(
            BT, QKVN, Dd, pxn, pwp + (size_t)l * Dd * QKVN, nullptr, nullptr, pqkv);
        rope_kernel<<<(Bb*Tt*Hh*32 + 255) / 256, 256>>>(pqkv);
        attn_kernel<<<dim3(Bb * Hh, 2), 128>>>(pqkv, patt);
        // x += att @ Wp[l] + bp[l]   (2048 x 384 x 384) — BM=64 for grid width
        tgemm_kernel<64, true, true,false,true>
            <<<dim3(Dd/128, BT/64), 128>>>(
            BT, Dd, Dd, patt, Wp + (size_t)l * Dd * Dd, bp + l * Dd, px, px);
        ln_kernel<<<BT, 128>>>(px, ln2g + l * Dd, ln2b + l * Dd, pxn);
        // h1 = relu(xn @ W1 + b1)    (2048 x 1536 x 384)
        tgemm_kernel<128, true, true,true,false>
            <<<dim3(FF/128, BT/128), 256>>>(
            BT, FF, Dd, pxn, W1 + (size_t)l * Dd * FF, b1 + l * FF, nullptr, ph1);
        // x += h1 @ W2 + b2          (2048 x 384 x 1536) — BM=64
        tgemm_kernel<64, true, true,false,true>
            <<<dim3(Dd/128, BT/64), 128>>>(
            BT, Dd, FF, ph1, W2 + (size_t)l * FF * Dd, b2 + l * Dd, px, px);
    }
    ln_kernel<<<BT, 128>>>(px, lnfg, lnfb, pxn);
    // logits = xn @ lmW + lmb        (2048 x 50257 x 384) — unaligned N
    tgemm_kernel<128, false, true,false,false>
        <<<dim3((Vv + 127)/128, BT/128), 256>>>(
        BT, Vv, Dd, pxn, lmW, lmb, nullptr, out);
}

// round 10
// speedup vs baseline: 1.8598x; 1.0375x over previous
#include <cuda_runtime.h>
#include <cuda_bf16.h>
#include <math.h>
#include <stdint.h>

// Problem constants
#define Vv 50257
#define Vp 50304            // Vv padded to multiple of 128
#define Dd 384
#define Hh 6
#define HSs 64
#define Ll 6
#define Tt 256
#define Bb 8
#define BT (Bb*Tt)          // 2048 rows
#define QKVN (3*Hh*HSs)     // 1152
#define FF (4*Dd)           // 1536

// -------- device scratch (no allocation allowed) --------
__device__ float g_x   [BT*Dd];
__device__ float g_xn  [BT*Dd];
__device__ float g_qkv [BT*QKVN];
__device__ float g_att [BT*Dd];
__device__ float g_h1  [BT*FF];
__device__ float g_wpk [Ll*Dd*QKVN];   // rounded packed qkv weights
__device__ float g_wpr [Ll*Dd*Dd];     // rounded Wp
__device__ float g_w1r [Ll*Dd*FF];     // rounded W1
__device__ float g_w2r [Ll*FF*Dd];     // rounded W2
__device__ float g_lmp [Dd*Vp];        // rounded+padded lmW

// ============================================================
// helpers
// ============================================================
__device__ __forceinline__ void cp_async16(void* dst, const void* src) {
    uint32_t s = (uint32_t)__cvta_generic_to_shared(dst);
    asm volatile("cp.async.cg.shared.global [%0], [%1], 16;\n" :: "r"(s), "l"(src));
}
#define CP_COMMIT() asm volatile("cp.async.commit_group;\n" ::: "memory")
#define CP_WAIT1()  asm volatile("cp.async.wait_group 1;\n" ::: "memory")
#define CP_WAIT0()  asm volatile("cp.async.wait_group 0;\n" ::: "memory")

__device__ __forceinline__ float tf32r(float x) {
    uint32_t u;
    asm("cvt.rna.tf32.f32 %0, %1;" : "=r"(u) : "f"(x));
    return __uint_as_float(u);
}

__device__ __forceinline__ void mma_tf32(float* c, const uint32_t* a,
                                         uint32_t b0, uint32_t b1) {
    asm volatile(
        "mma.sync.aligned.m16n8k8.row.col.f32.tf32.tf32.f32 "
        "{%0,%1,%2,%3}, {%4,%5,%6,%7}, {%8,%9}, {%0,%1,%2,%3};\n"
        : "+f"(c[0]), "+f"(c[1]), "+f"(c[2]), "+f"(c[3])
        : "r"(a[0]), "r"(a[1]), "r"(a[2]), "r"(a[3]), "r"(b0), "r"(b1));
}

// ============================================================
// Weight rounding / padding (runs every call; deterministic)
// ============================================================
__global__ void round_kernel(const float* __restrict__ s, float* __restrict__ d, int n) {
    int i = blockIdx.x * blockDim.x + threadIdx.x;
    if (i < n) d[i] = tf32r(s[i]);
}
__global__ void lmpad_kernel(const float* __restrict__ lmW, float* __restrict__ dst) {
    int n = blockIdx.x * 256 + threadIdx.x;   // 0..Vp-1  (grid.x = ceil(Vp/256))
    int k = blockIdx.y;                        // 0..Dd-1
    if (n < Vp)
        dst[(size_t)k * Vp + n] = (n < Vv) ? tf32r(lmW[(size_t)k * Vv + n]) : 0.0f;
}

// ============================================================
// Embedding
// ============================================================
__global__ void embed_kernel(const int* __restrict__ idx,
                             const float* __restrict__ tok,
                             float* __restrict__ x) {
    int gid = blockIdx.x * blockDim.x + threadIdx.x;
    if (gid >= BT * Dd) return;
    int row = gid / Dd;
    int d   = gid - row * Dd;
    x[gid] = tok[(size_t)idx[row] * Dd + d];
}

// ============================================================
// Pack Wq/Wk/Wv (L,H,D,HS) -> wpk[L][D][3*H*HS], tf32-rounded
// ============================================================
__global__ void pack_kernel(const float* __restrict__ Wq,
                            const float* __restrict__ Wk,
                            const float* __restrict__ Wv,
                            float* __restrict__ wp) {
    int gid = blockIdx.x * blockDim.x + threadIdx.x;
    const int total = Ll * Hh * Dd * HSs;
    if (gid >= total) return;
    int s = gid & (HSs - 1);
    int d = (gid >> 6) % Dd;
    int h = (gid / (HSs * Dd)) % Hh;
    int l = gid / (HSs * Dd * Hh);
    size_t src = (((size_t)(l * Hh + h) * Dd) + d) * HSs + s;
    size_t dstRow = (size_t)(l * Dd + d) * QKVN;
    int col = h * HSs + s;
    wp[dstRow + col]            = tf32r(Wq[src]);
    wp[dstRow + Dd + col]       = tf32r(Wk[src]);
    wp[dstRow + 2 * Dd + col]   = tf32r(Wv[src]);
}

// ============================================================
// LayerNorm (D=384), 128 threads/row — output tf32-rounded
// ============================================================
__global__ __launch_bounds__(128) void ln_kernel(const float* __restrict__ x,
                                                 const float* __restrict__ g,
                                                 const float* __restrict__ b,
                                                 float* __restrict__ y) {
    int row = blockIdx.x;
    const float* xr = x + (size_t)row * Dd;
    int tid = threadIdx.x;
    float v0 = xr[tid], v1 = xr[tid + 128], v2 = xr[tid + 256];
    float s = v0 + v1 + v2;
    __shared__ float red[4];
    #pragma unroll
    for (int o = 16; o; o >>= 1) s += __shfl_xor_sync(~0u, s, o);
    if ((tid & 31) == 0) red[tid >> 5] = s;
    __syncthreads();
    float mean = (red[0] + red[1] + red[2] + red[3]) * (1.0f / Dd);
    float d0 = v0 - mean, d1 = v1 - mean, d2 = v2 - mean;
    float q = d0 * d0 + d1 * d1 + d2 * d2;
    __syncthreads();
    #pragma unroll
    for (int o = 16; o; o >>= 1) q += __shfl_xor_sync(~0u, q, o);
    if ((tid & 31) == 0) red[tid >> 5] = q;
    __syncthreads();
    float var = (red[0] + red[1] + red[2] + red[3]) * (1.0f / Dd);
    float rstd = rsqrtf(var + 1e-5f);
    float* yr = y + (size_t)row * Dd;
    yr[tid]       = tf32r(d0 * rstd * g[tid]       + b[tid]);
    yr[tid + 128] = tf32r(d1 * rstd * g[tid + 128] + b[tid + 128]);
    yr[tid + 256] = tf32r(d2 * rstd * g[tid + 256] + b[tid + 256]);
}

// ============================================================
// RoPE (exact replica of reference semantics)
// ============================================================
__global__ void rope_kernel(float* __restrict__ qkv) {
    int gid = blockIdx.x * blockDim.x + threadIdx.x;
    const int total = Bb * Tt * Hh * 32;
    if (gid >= total) return;
    int i  = gid & 31;
    int h  = (gid >> 5) % Hh;
    int bt = gid / (32 * Hh);
    int t  = bt & (Tt - 1);
    const float lg = -9.210340371976184f / 64.0f;
    float S, C;
    float tf = (float)t;
    if ((i & 1) == 0) {
        S = sinf(tf * expf(lg * (float)i));
        C = sinf(tf * expf(lg * (float)(32 + i)));
    } else {
        S = cosf(tf * expf(lg * (float)(i - 1)));
        C = cosf(tf * expf(lg * (float)(31 + i)));
    }
    size_t rowq = (size_t)bt * QKVN + h * HSs;
    float qe = qkv[rowq + 2 * i], qo = qkv[rowq + 2 * i + 1];
    qkv[rowq + 2 * i]     = -qo * C;
    qkv[rowq + 2 * i + 1] =  qe * S;
    float* kp = qkv + rowq + Dd;
    float ke = kp[2 * i], ko = kp[2 * i + 1];
    kp[2 * i]     = -ko * C;
    kp[2 * i + 1] =  ke * S;
}

// ============================================================
// Fused causal attention — output tf32-rounded (feeds proj GEMM A)
// ============================================================
__global__ __launch_bounds__(128) void attn_kernel(const float* __restrict__ qkv,
                                                   float* __restrict__ att) {
    __shared__ __align__(16) float Ks[64 * 64];
    __shared__ __align__(16) float Vs[64 * 64];
    int b = blockIdx.x / Hh, h = blockIdx.x % Hh;
    int tid = threadIdx.x;
    int t = blockIdx.y * 128 + tid;
    size_t qrow = ((size_t)(b * Tt + t)) * QKVN + h * HSs;
    float qr[64];
    #pragma unroll
    for (int c = 0; c < 16; ++c) {
        float4 v = *(const float4*)(qkv + qrow + c * 4);
        qr[c*4+0] = v.x; qr[c*4+1] = v.y; qr[c*4+2] = v.z; qr[c*4+3] = v.w;
    }
    const float sc = 0.125f * 1.4426950408889634f;
    #pragma unroll
    for (int d = 0; d < 64; ++d) qr[d] *= sc;

    float mrun = -1e30f, ssum = 0.0f;
    float acc[64];
    #pragma unroll
    for (int d = 0; d < 64; ++d) acc[d] = 0.0f;

    int ntiles = blockIdx.y * 2 + 2;
    for (int tile = 0; tile < ntiles; ++tile) {
        #pragma unroll
        for (int u = 0; u < 8; ++u) {
            int e = tid + u * 128;
            int j = e >> 4;
            int c = (e & 15) << 2;
            size_t src = ((size_t)(b * Tt + tile * 64 + j)) * QKVN + h * HSs + c;
            *(float4*)(Ks + j * 64 + c) = *(const float4*)(qkv + src + Dd);
            *(float4*)(Vs + j * 64 + c) = *(const float4*)(qkv + src + 2 * Dd);
        }
        __syncthreads();
        int jmax = t - tile * 64;
        if (jmax > 63) jmax = 63;
        for (int jj = 0; jj <= jmax; ++jj) {
            const float* kr = Ks + jj * 64;
            float s = 0.0f;
            #pragma unroll
            for (int d = 0; d < 64; ++d) s += qr[d] * kr[d];
            const float* vr = Vs + jj * 64;
            if (s <= mrun) {
                float p = exp2f(s - mrun);
                ssum += p;
                #pragma unroll
                for (int d = 0; d < 64; ++d) acc[d] += p * vr[d];
            } else {
                float corr = exp2f(mrun - s);
                ssum = ssum * corr + 1.0f;
                #pragma unroll
                for (int d = 0; d < 64; ++d) acc[d] = acc[d] * corr + vr[d];
                mrun = s;
            }
        }
        __syncthreads();
    }
    float inv = 1.0f / ssum;
    float* op = att + ((size_t)(b * Tt + t)) * Dd + h * HSs;
    #pragma unroll
    for (int c = 0; c < 16; ++c) {
        float4 v;
        v.x = tf32r(acc[c*4] * inv);   v.y = tf32r(acc[c*4+1] * inv);
        v.z = tf32r(acc[c*4+2] * inv); v.w = tf32r(acc[c*4+3] * inv);
        *(float4*)(op + c * 4) = v;
    }
}

// ============================================================
// Pipelined tf32 tensor-core GEMM, 3-stage cp.async, dynamic smem.
// C(M x Nc) = A(M x K) @ B(K x Nb)[:, :Nc]  [+bias][+res][relu][round]
// Inputs A,B pre-rounded to tf32. Nb % 128 == 0, M % BM == 0, K % 16 == 0.
// BM=128: 256 thr (8 warps 4x2). BM=64: 128 thr (4 warps 2x2). Warptile 32x64.
// ============================================================
template<int BM, bool BIAS, bool RELU, bool RES, bool ROUND>
__global__ void __launch_bounds__(BM == 128 ? 256 : 128, BM == 128 ? 1 : 3)
tgemm_kernel(
    int M, int Nb, int Nc, int K,
    const float* __restrict__ A,
    const float* __restrict__ B,
    const float* __restrict__ bias,
    const float* __restrict__ res,
    float* __restrict__ C) {
    constexpr int BK = 16;
    constexpr int THREADS = (BM == 128) ? 256 : 128;
    constexpr int SA = 20;     // A row stride (conflict-free fragment LDS)
    constexpr int SB = 136;    // B row stride
    extern __shared__ float smem[];
    float* As = smem;                 // [3][BM][SA]
    float* Bs = smem + 3 * BM * SA;   // [3][BK][SB]

    int tid  = threadIdx.x;
    int warp = tid >> 5, lane = tid & 31;
    int gid  = lane >> 2, tig = lane & 3;
    int m0 = blockIdx.y * BM;
    int n0 = blockIdx.x * 128;
    int warpRow = (warp >> 1) * 32;
    int warpCol = (warp & 1) * 64;

    float c[2][8][4];
    #pragma unroll
    for (int im = 0; im < 2; ++im)
        #pragma unroll
        for (int in = 0; in < 8; ++in)
            #pragma unroll
            for (int r = 0; r < 4; ++r) c[im][in][r] = 0.0f;

    int nk = K / BK;

    auto load_tiles = [&](int kt, int buf) {
        int k0 = kt * BK;
        float* Ash = As + buf * BM * SA;
        float* Bsh = Bs + buf * BK * SB;
        #pragma unroll
        for (int u = 0; u < (BM * 4) / THREADS; ++u) {
            int q  = tid + u * THREADS;
            int r  = q >> 2;
            int c4 = (q & 3) * 4;
            cp_async16(Ash + r * SA + c4, A + (size_t)(m0 + r) * K + k0 + c4);
        }
        #pragma unroll
        for (int u = 0; u < 512 / THREADS; ++u) {
            int q  = tid + u * THREADS;
            int kk = q >> 5;
            int cc = (q & 31) * 4;
            cp_async16(Bsh + kk * SB + cc, B + (size_t)(k0 + kk) * Nb + n0 + cc);
        }
    };

    load_tiles(0, 0); CP_COMMIT();
    load_tiles(1, 1); CP_COMMIT();

    int buf = 0;
    for (int kt = 0; kt < nk; ++kt) {
        if (kt + 1 < nk) { CP_WAIT1(); } else { CP_WAIT0(); }
        __syncthreads();
        if (kt + 2 < nk) {
            load_tiles(kt + 2, buf == 0 ? 2 : buf - 1);  // (buf+2)%3
            CP_COMMIT();
        }
        const float* Ash = As + buf * BM * SA;
        const float* Bsh = Bs + buf * BK * SB;
        #pragma unroll
        for (int ks = 0; ks < 2; ++ks) {
            int kb = ks * 8;
            uint32_t a[2][4];
            #pragma unroll
            for (int im = 0; im < 2; ++im) {
                int mb = warpRow + im * 16;
                a[im][0] = __float_as_uint(Ash[(mb + gid    ) * SA + kb + tig    ]);
                a[im][1] = __float_as_uint(Ash[(mb + gid + 8) * SA + kb + tig    ]);
                a[im][2] = __float_as_uint(Ash[(mb + gid    ) * SA + kb + tig + 4]);
                a[im][3] = __float_as_uint(Ash[(mb + gid + 8) * SA + kb + tig + 4]);
            }
            #pragma unroll
            for (int in = 0; in < 8; ++in) {
                int nb = warpCol + in * 8 + gid;
                uint32_t b0 = __float_as_uint(Bsh[(kb + tig    ) * SB + nb]);
                uint32_t b1 = __float_as_uint(Bsh[(kb + tig + 4) * SB + nb]);
                mma_tf32(c[0][in], a[0], b0, b1);
                mma_tf32(c[1][in], a[1], b0, b1);
            }
        }
        buf = (buf == 2) ? 0 : buf + 1;
    }
    // epilogue
    #pragma unroll
    for (int im = 0; im < 2; ++im) {
        int mb = m0 + warpRow + im * 16 + gid;
        #pragma unroll
        for (int in = 0; in < 8; ++in) {
            int n = n0 + warpCol + in * 8 + tig * 2;
            #pragma unroll
            for (int j = 0; j < 2; ++j) {
                int nn = n + j;
                if (nn < Nc) {
                    float bv = BIAS ? bias[nn] : 0.0f;
                    float v0 = c[im][in][j]     + bv;
                    float v1 = c[im][in][j + 2] + bv;
                    int m1 = mb, m2 = mb + 8;
                    if (RES) {
                        v0 += res[(size_t)m1 * Nc + nn];
                        v1 += res[(size_t)m2 * Nc + nn];
                    }
                    if (RELU) { v0 = fmaxf(v0, 0.0f); v1 = fmaxf(v1, 0.0f); }
                    if (ROUND) { v0 = tf32r(v0); v1 = tf32r(v1); }
                    C[(size_t)m1 * Nc + nn] = v0;
                    C[(size_t)m2 * Nc + nn] = v1;
                }
            }
        }
    }
}

// ============================================================
// Host orchestration
// ============================================================
#define SMEM128 (3 * (128 * 20 + 16 * 136) * 4)   // 56832
#define SMEM64  (3 * ( 64 * 20 + 16 * 136) * 4)   // 41472

extern "C" void kernel_launch(void* const* d_in, const int* in_sizes, int n_in,
                              void* d_out, int out_size) {
    const int*   idx  = (const int*)  d_in[0];
    const float* tok  = (const float*)d_in[1];
    const float* Wq   = (const float*)d_in[2];
    const float* Wk   = (const float*)d_in[3];
    const float* Wv   = (const float*)d_in[4];
    const float* Wp   = (const float*)d_in[5];
    const float* bp   = (const float*)d_in[6];
    const float* W1   = (const float*)d_in[7];
    const float* b1   = (const float*)d_in[8];
    const float* W2   = (const float*)d_in[9];
    const float* b2   = (const float*)d_in[10];
    const float* ln1g = (const float*)d_in[11];
    const float* ln1b = (const float*)d_in[12];
    const float* ln2g = (const float*)d_in[13];
    const float* ln2b = (const float*)d_in[14];
    const float* lnfg = (const float*)d_in[15];
    const float* lnfb = (const float*)d_in[16];
    const float* lmW  = (const float*)d_in[17];
    const float* lmb  = (const float*)d_in[18];
    float* out = (float*)d_out;

    float *px, *pxn, *pqkv, *patt, *ph1, *pwp, *pwpr, *pw1r, *pw2r, *plmp;
    cudaGetSymbolAddress((void**)&px,   g_x);
    cudaGetSymbolAddress((void**)&pxn,  g_xn);
    cudaGetSymbolAddress((void**)&pqkv, g_qkv);
    cudaGetSymbolAddress((void**)&patt, g_att);
    cudaGetSymbolAddress((void**)&ph1,  g_h1);
    cudaGetSymbolAddress((void**)&pwp,  g_wpk);
    cudaGetSymbolAddress((void**)&pwpr, g_wpr);
    cudaGetSymbolAddress((void**)&pw1r, g_w1r);
    cudaGetSymbolAddress((void**)&pw2r, g_w2r);
    cudaGetSymbolAddress((void**)&plmp, g_lmp);

    // raise dynamic-smem limits (idempotent, not an allocation)
    cudaFuncSetAttribute((const void*)tgemm_kernel<128,false,false,false,false>,
                         cudaFuncAttributeMaxDynamicSharedMemorySize, SMEM128);
    cudaFuncSetAttribute((const void*)tgemm_kernel<128,true,true,false,true>,
                         cudaFuncAttributeMaxDynamicSharedMemorySize, SMEM128);
    cudaFuncSetAttribute((const void*)tgemm_kernel<128,true,false,false,false>,
                         cudaFuncAttributeMaxDynamicSharedMemorySize, SMEM128);
    cudaFuncSetAttribute((const void*)tgemm_kernel<64,true,false,true,false>,
                         cudaFuncAttributeMaxDynamicSharedMemorySize, SMEM64);

    // weight prep (every call; deterministic)
    pack_kernel<<<(Ll*Hh*Dd*HSs + 255) / 256, 256>>>(Wq, Wk, Wv, pwp);
    round_kernel<<<(Ll*Dd*Dd   + 255) / 256, 256>>>(Wp, pwpr, Ll*Dd*Dd);
    round_kernel<<<(Ll*Dd*FF   + 255) / 256, 256>>>(W1, pw1r, Ll*Dd*FF);
    round_kernel<<<(Ll*FF*Dd   + 255) / 256, 256>>>(W2, pw2r, Ll*FF*Dd);
    lmpad_kernel<<<dim3((Vp + 255) / 256, Dd), 256>>>(lmW, plmp);
    embed_kernel<<<(BT*Dd + 255) / 256, 256>>>(idx, tok, px);

    for (int l = 0; l < Ll; ++l) {
        ln_kernel<<<BT, 128>>>(px, ln1g + l * Dd, ln1b + l * Dd, pxn);
        // qkv = xn @ wpk[l]   (2048 x 1152 x 384)
        tgemm_kernel<128,false,false,false,false>
            <<<dim3(QKVN/128, BT/128), 256, SMEM128>>>(
            BT, QKVN, QKVN, Dd, pxn, pwp + (size_t)l * Dd * QKVN, nullptr, nullptr, pqkv);
        rope_kernel<<<(Bb*Tt*Hh*32 + 255) / 256, 256>>>(pqkv);
        attn_kernel<<<dim3(Bb * Hh, 2), 128>>>(pqkv, patt);
        // x += att @ Wp[l] + bp[l]   (2048 x 384 x 384)
        tgemm_kernel<64,true,false,true,false>
            <<<dim3(Dd/128, BT/64), 128, SMEM64>>>(
            BT, Dd, Dd, Dd, patt, pwpr + (size_t)l * Dd * Dd, bp + l * Dd, px, px);
        ln_kernel<<<BT, 128>>>(px, ln2g + l * Dd, ln2b + l * Dd, pxn);
        // h1 = round(relu(xn @ W1 + b1))   (2048 x 1536 x 384)
        tgemm_kernel<128,true,true,false,true>
            <<<dim3(FF/128, BT/128), 256, SMEM128>>>(
            BT, FF, FF, Dd, pxn, pw1r + (size_t)l * Dd * FF, b1 + l * FF, nullptr, ph1);
        // x += h1 @ W2 + b2   (2048 x 384 x 1536)
        tgemm_kernel<64,true,false,true,false>
            <<<dim3(Dd/128, BT/64), 128, SMEM64>>>(
            BT, Dd, Dd, FF, ph1, pw2r + (size_t)l * FF * Dd, b2 + l * Dd, px, px);
    }
    ln_kernel<<<BT, 128>>>(px, lnfg, lnfb, pxn);
    // logits = xn @ lmWpad + lmb   (2048 x 50304(pad)/50257 x 384)
    tgemm_kernel<128,true,false,false,false>
        <<<dim3(Vp/128, BT/128), 256, SMEM128>>>(
        BT, Vp, Vv, Dd, pxn, plmp, lmb, nullptr, out);
}

// round 11
// speedup vs baseline: 2.1666x; 1.1650x over previous
#include <cuda_runtime.h>
#include <cuda_bf16.h>
#include <math.h>
#include <stdint.h>

// Problem constants
#define Vv 50257
#define Vp 50304            // Vv padded to multiple of 128
#define Dd 384
#define Hh 6
#define HSs 64
#define Ll 6
#define Tt 256
#define Bb 8
#define BT (Bb*Tt)          // 2048 rows
#define QKVN (3*Hh*HSs)     // 1152
#define FF (4*Dd)           // 1536

// -------- device scratch (no allocation allowed) --------
__device__ float g_x   [BT*Dd];
__device__ float g_xn  [BT*Dd];
__device__ float g_qkv [BT*QKVN];
__device__ float g_att [BT*Dd];
__device__ float g_h1  [BT*FF];
__device__ float g_wpk [Ll*Dd*QKVN];   // rounded packed qkv weights
__device__ float g_wpr [Ll*Dd*Dd];     // rounded Wp
__device__ float g_w1r [Ll*Dd*FF];     // rounded W1
__device__ float g_w2r [Ll*FF*Dd];     // rounded W2
__device__ float g_lmp [Dd*Vp];        // rounded+padded lmW

// ============================================================
// helpers
// ============================================================
__device__ __forceinline__ void cp_async16(void* dst, const void* src) {
    uint32_t s = (uint32_t)__cvta_generic_to_shared(dst);
    asm volatile("cp.async.cg.shared.global [%0], [%1], 16;\n" :: "r"(s), "l"(src));
}
#define CP_COMMIT() asm volatile("cp.async.commit_group;\n" ::: "memory")
#define CP_WAIT1()  asm volatile("cp.async.wait_group 1;\n" ::: "memory")
#define CP_WAIT0()  asm volatile("cp.async.wait_group 0;\n" ::: "memory")

__device__ __forceinline__ float tf32r(float x) {
    uint32_t u;
    asm("cvt.rna.tf32.f32 %0, %1;" : "=r"(u) : "f"(x));
    return __uint_as_float(u);
}

__device__ __forceinline__ void mma_tf32(float* c, const uint32_t* a,
                                         uint32_t b0, uint32_t b1) {
    asm volatile(
        "mma.sync.aligned.m16n8k8.row.col.f32.tf32.tf32.f32 "
        "{%0,%1,%2,%3}, {%4,%5,%6,%7}, {%8,%9}, {%0,%1,%2,%3};\n"
        : "+f"(c[0]), "+f"(c[1]), "+f"(c[2]), "+f"(c[3])
        : "r"(a[0]), "r"(a[1]), "r"(a[2]), "r"(a[3]), "r"(b0), "r"(b1));
}

// ============================================================
// Weight rounding / padding (runs every call; deterministic)
// ============================================================
__global__ void round_kernel(const float4* __restrict__ s, float4* __restrict__ d, int n4) {
    int i = blockIdx.x * blockDim.x + threadIdx.x;
    if (i < n4) {
        float4 v = s[i];
        v.x = tf32r(v.x); v.y = tf32r(v.y);
        v.z = tf32r(v.z); v.w = tf32r(v.w);
        d[i] = v;
    }
}
__global__ void lmpad_kernel(const float* __restrict__ lmW, float* __restrict__ dst) {
    int n4 = (blockIdx.x * 256 + threadIdx.x) * 4;   // grid.x = ceil(Vp/1024)
    int k = blockIdx.y;                              // 0..Dd-1
    if (n4 >= Vp) return;
    const float* srow = lmW + (size_t)k * Vv;
    float4 w;
    w.x = (n4 + 0 < Vv) ? tf32r(srow[n4 + 0]) : 0.0f;
    w.y = (n4 + 1 < Vv) ? tf32r(srow[n4 + 1]) : 0.0f;
    w.z = (n4 + 2 < Vv) ? tf32r(srow[n4 + 2]) : 0.0f;
    w.w = (n4 + 3 < Vv) ? tf32r(srow[n4 + 3]) : 0.0f;
    *(float4*)(dst + (size_t)k * Vp + n4) = w;
}

// ============================================================
// Embedding
// ============================================================
__global__ void embed_kernel(const int* __restrict__ idx,
                             const float* __restrict__ tok,
                             float* __restrict__ x) {
    int gid = blockIdx.x * blockDim.x + threadIdx.x;
    if (gid >= BT * Dd) return;
    int row = gid / Dd;
    int d   = gid - row * Dd;
    x[gid] = tok[(size_t)idx[row] * Dd + d];
}

// ============================================================
// Pack Wq/Wk/Wv (L,H,D,HS) -> wpk[L][D][3*H*HS], tf32-rounded
// ============================================================
__global__ void pack_kernel(const float* __restrict__ Wq,
                            const float* __restrict__ Wk,
                            const float* __restrict__ Wv,
                            float* __restrict__ wp) {
    int gid = blockIdx.x * blockDim.x + threadIdx.x;
    const int total = Ll * Hh * Dd * HSs;
    if (gid >= total) return;
    int s = gid & (HSs - 1);
    int d = (gid >> 6) % Dd;
    int h = (gid / (HSs * Dd)) % Hh;
    int l = gid / (HSs * Dd * Hh);
    size_t src = (((size_t)(l * Hh + h) * Dd) + d) * HSs + s;
    size_t dstRow = (size_t)(l * Dd + d) * QKVN;
    int col = h * HSs + s;
    wp[dstRow + col]            = tf32r(Wq[src]);
    wp[dstRow + Dd + col]       = tf32r(Wk[src]);
    wp[dstRow + 2 * Dd + col]   = tf32r(Wv[src]);
}

// ============================================================
// LayerNorm (D=384), 128 threads/row — output tf32-rounded
// ============================================================
__global__ __launch_bounds__(128) void ln_kernel(const float* __restrict__ x,
                                                 const float* __restrict__ g,
                                                 const float* __restrict__ b,
                                                 float* __restrict__ y) {
    int row = blockIdx.x;
    const float* xr = x + (size_t)row * Dd;
    int tid = threadIdx.x;
    float v0 = xr[tid], v1 = xr[tid + 128], v2 = xr[tid + 256];
    float s = v0 + v1 + v2;
    __shared__ float red[4];
    #pragma unroll
    for (int o = 16; o; o >>= 1) s += __shfl_xor_sync(~0u, s, o);
    if ((tid & 31) == 0) red[tid >> 5] = s;
    __syncthreads();
    float mean = (red[0] + red[1] + red[2] + red[3]) * (1.0f / Dd);
    float d0 = v0 - mean, d1 = v1 - mean, d2 = v2 - mean;
    float q = d0 * d0 + d1 * d1 + d2 * d2;
    __syncthreads();
    #pragma unroll
    for (int o = 16; o; o >>= 1) q += __shfl_xor_sync(~0u, q, o);
    if ((tid & 31) == 0) red[tid >> 5] = q;
    __syncthreads();
    float var = (red[0] + red[1] + red[2] + red[3]) * (1.0f / Dd);
    float rstd = rsqrtf(var + 1e-5f);
    float* yr = y + (size_t)row * Dd;
    yr[tid]       = tf32r(d0 * rstd * g[tid]       + b[tid]);
    yr[tid + 128] = tf32r(d1 * rstd * g[tid + 128] + b[tid + 128]);
    yr[tid + 256] = tf32r(d2 * rstd * g[tid + 256] + b[tid + 256]);
}

// ============================================================
// RoPE (exact replica of reference semantics)
// ============================================================
__global__ void rope_kernel(float* __restrict__ qkv) {
    int gid = blockIdx.x * blockDim.x + threadIdx.x;
    const int total = Bb * Tt * Hh * 32;
    if (gid >= total) return;
    int i  = gid & 31;
    int h  = (gid >> 5) % Hh;
    int bt = gid / (32 * Hh);
    int t  = bt & (Tt - 1);
    const float lg = -9.210340371976184f / 64.0f;
    float S, C;
    float tf = (float)t;
    if ((i & 1) == 0) {
        S = sinf(tf * expf(lg * (float)i));
        C = sinf(tf * expf(lg * (float)(32 + i)));
    } else {
        S = cosf(tf * expf(lg * (float)(i - 1)));
        C = cosf(tf * expf(lg * (float)(31 + i)));
    }
    size_t rowq = (size_t)bt * QKVN + h * HSs;
    float qe = qkv[rowq + 2 * i], qo = qkv[rowq + 2 * i + 1];
    qkv[rowq + 2 * i]     = -qo * C;
    qkv[rowq + 2 * i + 1] =  qe * S;
    float* kp = qkv + rowq + Dd;
    float ke = kp[2 * i], ko = kp[2 * i + 1];
    kp[2 * i]     = -ko * C;
    kp[2 * i + 1] =  ke * S;
}

// ============================================================
// Fused causal attention — output tf32-rounded (feeds proj GEMM A)
// ============================================================
__global__ __launch_bounds__(128) void attn_kernel(const float* __restrict__ qkv,
                                                   float* __restrict__ att) {
    __shared__ __align__(16) float Ks[64 * 64];
    __shared__ __align__(16) float Vs[64 * 64];
    int b = blockIdx.x / Hh, h = blockIdx.x % Hh;
    int tid = threadIdx.x;
    int t = blockIdx.y * 128 + tid;
    size_t qrow = ((size_t)(b * Tt + t)) * QKVN + h * HSs;
    float qr[64];
    #pragma unroll
    for (int c = 0; c < 16; ++c) {
        float4 v = *(const float4*)(qkv + qrow + c * 4);
        qr[c*4+0] = v.x; qr[c*4+1] = v.y; qr[c*4+2] = v.z; qr[c*4+3] = v.w;
    }
    const float sc = 0.125f * 1.4426950408889634f;
    #pragma unroll
    for (int d = 0; d < 64; ++d) qr[d] *= sc;

    float mrun = -1e30f, ssum = 0.0f;
    float acc[64];
    #pragma unroll
    for (int d = 0; d < 64; ++d) acc[d] = 0.0f;

    int ntiles = blockIdx.y * 2 + 2;
    for (int tile = 0; tile < ntiles; ++tile) {
        #pragma unroll
        for (int u = 0; u < 8; ++u) {
            int e = tid + u * 128;
            int j = e >> 4;
            int c = (e & 15) << 2;
            size_t src = ((size_t)(b * Tt + tile * 64 + j)) * QKVN + h * HSs + c;
            *(float4*)(Ks + j * 64 + c) = *(const float4*)(qkv + src + Dd);
            *(float4*)(Vs + j * 64 + c) = *(const float4*)(qkv + src + 2 * Dd);
        }
        __syncthreads();
        int jmax = t - tile * 64;
        if (jmax > 63) jmax = 63;
        for (int jj = 0; jj <= jmax; ++jj) {
            const float* kr = Ks + jj * 64;
            float s = 0.0f;
            #pragma unroll
            for (int d = 0; d < 64; ++d) s += qr[d] * kr[d];
            const float* vr = Vs + jj * 64;
            if (s <= mrun) {
                float p = exp2f(s - mrun);
                ssum += p;
                #pragma unroll
                for (int d = 0; d < 64; ++d) acc[d] += p * vr[d];
            } else {
                float corr = exp2f(mrun - s);
                ssum = ssum * corr + 1.0f;
                #pragma unroll
                for (int d = 0; d < 64; ++d) acc[d] = acc[d] * corr + vr[d];
                mrun = s;
            }
        }
        __syncthreads();
    }
    float inv = 1.0f / ssum;
    float* op = att + ((size_t)(b * Tt + t)) * Dd + h * HSs;
    #pragma unroll
    for (int c = 0; c < 16; ++c) {
        float4 v;
        v.x = tf32r(acc[c*4] * inv);   v.y = tf32r(acc[c*4+1] * inv);
        v.z = tf32r(acc[c*4+2] * inv); v.w = tf32r(acc[c*4+3] * inv);
        *(float4*)(op + c * 4) = v;
    }
}

// ============================================================
// Pipelined tf32 tensor-core GEMM, BK=32, 3-stage cp.async,
// register fragment double-buffering. Dynamic smem.
// C(M x Nc) = A(M x K) @ B(K x Nb)[:, :Nc]  [+bias][+res][relu][round]
// Inputs A,B pre-rounded to tf32. Nb % 128 == 0, M % BM == 0, K % 32 == 0.
// BM=128: 256 thr (8 warps 4x2). BM=64: 128 thr (4 warps 2x2). Warptile 32x64.
// ============================================================
template<int BM, bool BIAS, bool RELU, bool RES, bool ROUND>
__global__ void __launch_bounds__(BM == 128 ? 256 : 128)
tgemm_kernel(
    int M, int Nb, int Nc, int K,
    const float* __restrict__ A,
    const float* __restrict__ B,
    const float* __restrict__ bias,
    const float* __restrict__ res,
    float* __restrict__ C) {
    constexpr int BK = 32;
    constexpr int THREADS = (BM == 128) ? 256 : 128;
    constexpr int SA = BK + 4;   // 36: conflict-free fragment LDS; 144B row, 16B-aligned
    constexpr int SB = 136;      // 544B row, 16B-aligned
    extern __shared__ float smem[];
    float* As = smem;                 // [3][BM][SA]
    float* Bs = smem + 3 * BM * SA;   // [3][BK][SB]

    int tid  = threadIdx.x;
    int warp = tid >> 5, lane = tid & 31;
    int gid  = lane >> 2, tig = lane & 3;
    int m0 = blockIdx.y * BM;
    int n0 = blockIdx.x * 128;
    int warpRow = (warp >> 1) * 32;
    int warpCol = (warp & 1) * 64;

    float c[2][8][4];
    #pragma unroll
    for (int im = 0; im < 2; ++im)
        #pragma unroll
        for (int in = 0; in < 8; ++in)
            #pragma unroll
            for (int r = 0; r < 4; ++r) c[im][in][r] = 0.0f;

    int nk = K / BK;

    auto load_tiles = [&](int kt, int stage) {
        int k0 = kt * BK;
        float* Ash = As + stage * BM * SA;
        float* Bsh = Bs + stage * BK * SB;
        // A tile: BM x 32 floats = BM*8 16B-chunks
        #pragma unroll
        for (int u = 0; u < (BM * 8) / THREADS; ++u) {
            int q  = tid + u * THREADS;
            int r  = q >> 3;
            int c4 = (q & 7) * 4;
            cp_async16(Ash + r * SA + c4, A + (size_t)(m0 + r) * K + k0 + c4);
        }
        // B tile: 32 x 128 floats = 1024 16B-chunks
        #pragma unroll
        for (int u = 0; u < 1024 / THREADS; ++u) {
            int q  = tid + u * THREADS;
            int kk = q >> 5;
            int cc = (q & 31) * 4;
            cp_async16(Bsh + kk * SB + cc, B + (size_t)(k0 + kk) * Nb + n0 + cc);
        }
    };

    load_tiles(0, 0); CP_COMMIT();
    if (nk > 1) { load_tiles(1, 1); CP_COMMIT(); }

    int buf = 0;
    for (int kt = 0; kt < nk; ++kt) {
        if (kt + 1 < nk) { CP_WAIT1(); } else { CP_WAIT0(); }
        __syncthreads();
        if (kt + 2 < nk) {
            load_tiles(kt + 2, buf == 0 ? 2 : buf - 1);  // (buf+2)%3
            CP_COMMIT();
        }
        const float* Ash = As + buf * BM * SA;
        const float* Bsh = Bs + buf * BK * SB;

        auto ldA = [&](int ks, uint32_t (*a)[4]) {
            int kb = ks * 8;
            #pragma unroll
            for (int im = 0; im < 2; ++im) {
                int mb = warpRow + im * 16;
                a[im][0] = __float_as_uint(Ash[(mb + gid    ) * SA + kb + tig    ]);
                a[im][1] = __float_as_uint(Ash[(mb + gid + 8) * SA + kb + tig    ]);
                a[im][2] = __float_as_uint(Ash[(mb + gid    ) * SA + kb + tig + 4]);
                a[im][3] = __float_as_uint(Ash[(mb + gid + 8) * SA + kb + tig + 4]);
            }
        };
        auto ldB = [&](int ks, uint32_t* bf) {
            int kb = ks * 8;
            #pragma unroll
            for (int in = 0; in < 8; ++in) {
                int nb = warpCol + in * 8 + gid;
                bf[in * 2]     = __float_as_uint(Bsh[(kb + tig    ) * SB + nb]);
                bf[in * 2 + 1] = __float_as_uint(Bsh[(kb + tig + 4) * SB + nb]);
            }
        };

        uint32_t af[2][2][4];
        uint32_t bfb[2][16];
        ldA(0, af[0]);
        ldB(0, bfb[0]);
        #pragma unroll
        for (int ks = 0; ks < 4; ++ks) {
            int cb = ks & 1;
            if (ks < 3) {
                ldA(ks + 1, af[cb ^ 1]);
                ldB(ks + 1, bfb[cb ^ 1]);
            }
            #pragma unroll
            for (int in = 0; in < 8; ++in) {
                mma_tf32(c[0][in], af[cb][0], bfb[cb][in * 2], bfb[cb][in * 2 + 1]);
                mma_tf32(c[1][in], af[cb][1], bfb[cb][in * 2], bfb[cb][in * 2 + 1]);
            }
        }
        buf = (buf == 2) ? 0 : buf + 1;
    }
    // epilogue
    #pragma unroll
    for (int im = 0; im < 2; ++im) {
        int mb = m0 + warpRow + im * 16 + gid;
        #pragma unroll
        for (int in = 0; in < 8; ++in) {
            int n = n0 + warpCol + in * 8 + tig * 2;
            #pragma unroll
            for (int j = 0; j < 2; ++j) {
                int nn = n + j;
                if (nn < Nc) {
                    float bv = BIAS ? bias[nn] : 0.0f;
                    float v0 = c[im][in][j]     + bv;
                    float v1 = c[im][in][j + 2] + bv;
                    int m1 = mb, m2 = mb + 8;
                    if (RES) {
                        v0 += res[(size_t)m1 * Nc + nn];
                        v1 += res[(size_t)m2 * Nc + nn];
                    }
                    if (RELU) { v0 = fmaxf(v0, 0.0f); v1 = fmaxf(v1, 0.0f); }
                    if (ROUND) { v0 = tf32r(v0); v1 = tf32r(v1); }
                    C[(size_t)m1 * Nc + nn] = v0;
                    C[(size_t)m2 * Nc + nn] = v1;
                }
            }
        }
    }
}

// ============================================================
// Host orchestration
// ============================================================
#define SMEM128 (3 * (128 * 36 + 32 * 136) * 4)   // 107520
#define SMEM64  (3 * ( 64 * 36 + 32 * 136) * 4)   // 79872

extern "C" void kernel_launch(void* const* d_in, const int* in_sizes, int n_in,
                              void* d_out, int out_size) {
    const int*   idx  = (const int*)  d_in[0];
    const float* tok  = (const float*)d_in[1];
    const float* Wq   = (const float*)d_in[2];
    const float* Wk   = (const float*)d_in[3];
    const float* Wv   = (const float*)d_in[4];
    const float* Wp   = (const float*)d_in[5];
    const float* bp   = (const float*)d_in[6];
    const float* W1   = (const float*)d_in[7];
    const float* b1   = (const float*)d_in[8];
    const float* W2   = (const float*)d_in[9];
    const float* b2   = (const float*)d_in[10];
    const float* ln1g = (const float*)d_in[11];
    const float* ln1b = (const float*)d_in[12];
    const float* ln2g = (const float*)d_in[13];
    const float* ln2b = (const float*)d_in[14];
    const float* lnfg = (const float*)d_in[15];
    const float* lnfb = (const float*)d_in[16];
    const float* lmW  = (const float*)d_in[17];
    const float* lmb  = (const float*)d_in[18];
    float* out = (float*)d_out;

    float *px, *pxn, *pqkv, *patt, *ph1, *pwp, *pwpr, *pw1r, *pw2r, *plmp;
    cudaGetSymbolAddress((void**)&px,   g_x);
    cudaGetSymbolAddress((void**)&pxn,  g_xn);
    cudaGetSymbolAddress((void**)&pqkv, g_qkv);
    cudaGetSymbolAddress((void**)&patt, g_att);
    cudaGetSymbolAddress((void**)&ph1,  g_h1);
    cudaGetSymbolAddress((void**)&pwp,  g_wpk);
    cudaGetSymbolAddress((void**)&pwpr, g_wpr);
    cudaGetSymbolAddress((void**)&pw1r, g_w1r);
    cudaGetSymbolAddress((void**)&pw2r, g_w2r);
    cudaGetSymbolAddress((void**)&plmp, g_lmp);

    // raise dynamic-smem limits (idempotent, not an allocation)
    cudaFuncSetAttribute((const void*)tgemm_kernel<128,false,false,false,false>,
                         cudaFuncAttributeMaxDynamicSharedMemorySize, SMEM128);
    cudaFuncSetAttribute((const void*)tgemm_kernel<128,true,true,false,true>,
                         cudaFuncAttributeMaxDynamicSharedMemorySize, SMEM128);
    cudaFuncSetAttribute((const void*)tgemm_kernel<128,true,false,false,false>,
                         cudaFuncAttributeMaxDynamicSharedMemorySize, SMEM128);
    cudaFuncSetAttribute((const void*)tgemm_kernel<64,true,false,true,false>,
                         cudaFuncAttributeMaxDynamicSharedMemorySize, SMEM64);

    // weight prep (every call; deterministic)
    pack_kernel<<<(Ll*Hh*Dd*HSs + 255) / 256, 256>>>(Wq, Wk, Wv, pwp);
    round_kernel<<<(Ll*Dd*Dd/4 + 255) / 256, 256>>>((const float4*)Wp, (float4*)pwpr, Ll*Dd*Dd/4);
    round_kernel<<<(Ll*Dd*FF/4 + 255) / 256, 256>>>((const float4*)W1, (float4*)pw1r, Ll*Dd*FF/4);
    round_kernel<<<(Ll*FF*Dd/4 + 255) / 256, 256>>>((const float4*)W2, (float4*)pw2r, Ll*FF*Dd/4);
    lmpad_kernel<<<dim3((Vp/4 + 255) / 256, Dd), 256>>>(lmW, plmp);
    embed_kernel<<<(BT*Dd + 255) / 256, 256>>>(idx, tok, px);

    for (int l = 0; l < Ll; ++l) {
        ln_kernel<<<BT, 128>>>(px, ln1g + l * Dd, ln1b + l * Dd, pxn);
        // qkv = xn @ wpk[l]   (2048 x 1152 x 384)
        tgemm_kernel<128,false,false,false,false>
            <<<dim3(QKVN/128, BT/128), 256, SMEM128>>>(
            BT, QKVN, QKVN, Dd, pxn, pwp + (size_t)l * Dd * QKVN, nullptr, nullptr, pqkv);
        rope_kernel<<<(Bb*Tt*Hh*32 + 255) / 256, 256>>>(pqkv);
        attn_kernel<<<dim3(Bb * Hh, 2), 128>>>(pqkv, patt);
        // x += att @ Wp[l] + bp[l]   (2048 x 384 x 384)
        tgemm_kernel<64,true,false,true,false>
            <<<dim3(Dd/128, BT/64), 128, SMEM64>>>(
            BT, Dd, Dd, Dd, patt, pwpr + (size_t)l * Dd * Dd, bp + l * Dd, px, px);
        ln_kernel<<<BT, 128>>>(px, ln2g + l * Dd, ln2b + l * Dd, pxn);
        // h1 = round(relu(xn @ W1 + b1))   (2048 x 1536 x 384)
        tgemm_kernel<128,true,true,false,true>
            <<<dim3(FF/128, BT/128), 256, SMEM128>>>(
            BT, FF, FF, Dd, pxn, pw1r + (size_t)l * Dd * FF, b1 + l * FF, nullptr, ph1);
        // x += h1 @ W2 + b2   (2048 x 384 x 1536)
        tgemm_kernel<64,true,false,true,false>
            <<<dim3(Dd/128, BT/64), 128, SMEM64>>>(
            BT, Dd, Dd, FF, ph1, pw2r + (size_t)l * FF * Dd, b2 + l * Dd, px, px);
    }
    ln_kernel<<<BT, 128>>>(px, lnfg, lnfb, pxn);
    // logits = xn @ lmWpad + lmb   (2048 x 50304(pad)/50257 x 384)
    tgemm_kernel<128,true,false,false,false>
        <<<dim3(Vp/128, BT/128), 256, SMEM128>>>(
        BT, Vp, Vv, Dd, pxn, plmp, lmb, nullptr, out);
}